// round 6
// baseline (speedup 1.0000x reference)
#include <cuda_runtime.h>

// Problem constants
static constexpr int B_  = 16;
static constexpr int N_  = 3136;   // 56*56
static constexpr int C_  = 768;
static constexpr int H_  = 12;
static constexpr int D_  = 64;
static constexpr int M_  = B_ * N_;          // 50176
static constexpr int QC_ = 3 * C_;           // 2304

// Scratch (static device globals: allocation-free at runtime)
__device__ float g_qkv[(size_t)M_ * QC_];          // [M, 2304]
__device__ float g_ctx[(size_t)B_ * H_ * D_ * D_]; // [B*H,64,64]
__device__ float g_img[(size_t)B_ * C_ * N_];      // [B,C,N] attn out (channel-major)
__device__ float g_cnv[(size_t)B_ * C_ * N_];      // [B,C,N] conv out

// ---------------------------------------------------------------------------
// Kernel 1: QKV GEMM  g_qkv[M,2304] = x[M,768] @ qkv_w[768,2304] + qkv_b
// 128x128x16 tile, 256 threads, 8x8 microtile, double-buffered smem.
// ---------------------------------------------------------------------------
__global__ __launch_bounds__(256, 2) void qkv_gemm_kernel(
    const float* __restrict__ A, const float* __restrict__ W,
    const float* __restrict__ bias)
{
    constexpr int BK = 16;
    __shared__ float As[2][BK][132];   // [k][m], padded
    __shared__ float Bs[2][BK][128];   // [k][n]

    const int tid = threadIdx.x;
    const int m0 = blockIdx.y * 128;
    const int n0 = blockIdx.x * 128;

    const int tr = (tid >> 4) * 8;      // microtile row base
    const int tc = (tid & 15) * 8;      // microtile col base

    const int aRow = tid >> 1;          // m 0..127
    const int aCol = (tid & 1) * 8;     // k 0 or 8
    const int bRow = tid >> 4;          // k 0..15
    const int bCol = (tid & 15) * 8;    // n 0..120

    const float* Ap = A + (size_t)(m0 + aRow) * 768 + aCol;
    const float* Wp = W + (size_t)bRow * QC_ + n0 + bCol;

    float4 fa0 = *(const float4*)(Ap);
    float4 fa1 = *(const float4*)(Ap + 4);
    float4 fb0 = *(const float4*)(Wp);
    float4 fb1 = *(const float4*)(Wp + 4);

    float acc[8][8];
#pragma unroll
    for (int i = 0; i < 8; i++)
#pragma unroll
        for (int j = 0; j < 8; j++) acc[i][j] = 0.f;

    // store tile 0 -> buf 0 (A transposed)
    As[0][aCol + 0][aRow] = fa0.x;
    As[0][aCol + 1][aRow] = fa0.y;
    As[0][aCol + 2][aRow] = fa0.z;
    As[0][aCol + 3][aRow] = fa0.w;
    As[0][aCol + 4][aRow] = fa1.x;
    As[0][aCol + 5][aRow] = fa1.y;
    As[0][aCol + 6][aRow] = fa1.z;
    As[0][aCol + 7][aRow] = fa1.w;
    *(float4*)&Bs[0][bRow][bCol]     = fb0;
    *(float4*)&Bs[0][bRow][bCol + 4] = fb1;
    __syncthreads();

    int buf = 0;
    for (int kt = 0; kt < 768; kt += BK) {
        const int ktn = kt + BK;
        if (ktn < 768) {
            fa0 = *(const float4*)(Ap + ktn);
            fa1 = *(const float4*)(Ap + ktn + 4);
            fb0 = *(const float4*)(Wp + (size_t)ktn * QC_);
            fb1 = *(const float4*)(Wp + (size_t)ktn * QC_ + 4);
        }

#pragma unroll
        for (int k = 0; k < BK; k++) {
            float ra[8], rb[8];
            *(float4*)&ra[0] = *(const float4*)&As[buf][k][tr];
            *(float4*)&ra[4] = *(const float4*)&As[buf][k][tr + 4];
            *(float4*)&rb[0] = *(const float4*)&Bs[buf][k][tc];
            *(float4*)&rb[4] = *(const float4*)&Bs[buf][k][tc + 4];
#pragma unroll
            for (int i = 0; i < 8; i++)
#pragma unroll
                for (int j = 0; j < 8; j++) acc[i][j] += ra[i] * rb[j];
        }

        if (ktn < 768) {
            const int nb = buf ^ 1;
            As[nb][aCol + 0][aRow] = fa0.x;
            As[nb][aCol + 1][aRow] = fa0.y;
            As[nb][aCol + 2][aRow] = fa0.z;
            As[nb][aCol + 3][aRow] = fa0.w;
            As[nb][aCol + 4][aRow] = fa1.x;
            As[nb][aCol + 5][aRow] = fa1.y;
            As[nb][aCol + 6][aRow] = fa1.z;
            As[nb][aCol + 7][aRow] = fa1.w;
            *(float4*)&Bs[nb][bRow][bCol]     = fb0;
            *(float4*)&Bs[nb][bRow][bCol + 4] = fb1;
            __syncthreads();
            buf = nb;
        }
    }

    float bb[8];
#pragma unroll
    for (int j = 0; j < 8; j++) bb[j] = bias[n0 + tc + j];

#pragma unroll
    for (int i = 0; i < 8; i++) {
        size_t ob = (size_t)(m0 + tr + i) * QC_ + n0 + tc;
        float4 v0, v1;
        v0.x = acc[i][0] + bb[0]; v0.y = acc[i][1] + bb[1];
        v0.z = acc[i][2] + bb[2]; v0.w = acc[i][3] + bb[3];
        v1.x = acc[i][4] + bb[4]; v1.y = acc[i][5] + bb[5];
        v1.z = acc[i][6] + bb[6]; v1.w = acc[i][7] + bb[7];
        *(float4*)&g_qkv[ob]     = v0;
        *(float4*)&g_qkv[ob + 4] = v1;
    }
}

// ---------------------------------------------------------------------------
// Kernel 2: context[b,h] = relu(k)^T @ v   ([64,64] per (b,h))
// One block per (b,h): 192 blocks, 256 threads, 4x4 accum per thread.
// ---------------------------------------------------------------------------
__global__ __launch_bounds__(256) void ctx_kernel()
{
    const int bh = blockIdx.x;
    const int b = bh / H_;
    const int h = bh - b * H_;
    const int tid = threadIdx.x;

    __shared__ float ks[32][64];
    __shared__ float vs[32][64];

    float acc[4][4];
#pragma unroll
    for (int i = 0; i < 4; i++)
#pragma unroll
        for (int j = 0; j < 4; j++) acc[i][j] = 0.f;

    const int rg = (tid >> 4) * 4;   // d rows (k dim)
    const int cg = (tid & 15) * 4;   // e cols (v dim)

    const size_t kbase = (size_t)b * N_ * QC_ + 768 + h * 64;

    for (int nt = 0; nt < N_; nt += 32) {
#pragma unroll
        for (int i = 0; i < 2; i++) {
            int idx = tid + i * 256;
            int row = idx >> 4;
            int col = (idx & 15) * 4;
            size_t p = kbase + (size_t)(nt + row) * QC_ + col;
            float4 kv = *(const float4*)(g_qkv + p);
            float4 vv = *(const float4*)(g_qkv + p + 768);
            kv.x = fmaxf(kv.x, 0.f); kv.y = fmaxf(kv.y, 0.f);
            kv.z = fmaxf(kv.z, 0.f); kv.w = fmaxf(kv.w, 0.f);
            *(float4*)&ks[row][col] = kv;
            *(float4*)&vs[row][col] = vv;
        }
        __syncthreads();

#pragma unroll 8
        for (int nn = 0; nn < 32; nn++) {
            float kr[4], vr[4];
            *(float4*)kr = *(const float4*)&ks[nn][rg];
            *(float4*)vr = *(const float4*)&vs[nn][cg];
#pragma unroll
            for (int i = 0; i < 4; i++)
#pragma unroll
                for (int j = 0; j < 4; j++) acc[i][j] += kr[i] * vr[j];
        }
        __syncthreads();
    }

    size_t ob = (size_t)bh * (D_ * D_);
#pragma unroll
    for (int i = 0; i < 4; i++) {
        float4 v;
        v.x = acc[i][0]; v.y = acc[i][1]; v.z = acc[i][2]; v.w = acc[i][3];
        *(float4*)&g_ctx[ob + (size_t)(rg + i) * 64 + cg] = v;
    }
}

// ---------------------------------------------------------------------------
// Kernel 3: out[b, h*64+e, n] = sum_d relu(q[b,n,h,d])*scale * ctx[b,h,d,e]
// Writes channel-major [B, C, N] so conv + proj GEMM read coalesced.
// ---------------------------------------------------------------------------
__global__ __launch_bounds__(256) void attn_out_kernel()
{
    const int n0 = blockIdx.x * 128;
    const int h  = blockIdx.y;
    const int b  = blockIdx.z;
    const int tid = threadIdx.x;

    __shared__ float cs[64][64];    // ctx [d][e]
    __shared__ float qs[64][129];   // q^T [d][n], padded

    const size_t cb = (size_t)(b * H_ + h) * (D_ * D_);
#pragma unroll
    for (int i = 0; i < 4; i++) {
        int idx = tid + i * 256;
        ((float4*)&cs[0][0])[idx] = ((const float4*)(g_ctx + cb))[idx];
    }

    const float scale = 0.125f;  // 64^-0.5
#pragma unroll
    for (int i = 0; i < 32; i++) {
        int idx = tid + i * 256;
        int d  = idx & 63;
        int nn = idx >> 6;
        int n  = n0 + nn;
        float v = 0.f;
        if (n < N_)
            v = g_qkv[(size_t)(b * N_ + n) * QC_ + h * 64 + d];
        qs[d][nn] = fmaxf(v, 0.f) * scale;
    }
    __syncthreads();

    const int lane = tid & 31;
    const int e0 = (tid >> 5) * 8;
    float acc[8][4];
#pragma unroll
    for (int i = 0; i < 8; i++)
#pragma unroll
        for (int k = 0; k < 4; k++) acc[i][k] = 0.f;

#pragma unroll 4
    for (int dd = 0; dd < 64; dd++) {
        float qv[4];
#pragma unroll
        for (int k = 0; k < 4; k++) qv[k] = qs[dd][lane + 32 * k];
#pragma unroll
        for (int i = 0; i < 8; i++) {
            float ce = cs[dd][e0 + i];
#pragma unroll
            for (int k = 0; k < 4; k++) acc[i][k] += ce * qv[k];
        }
    }

    const size_t ob = ((size_t)b * C_ + h * 64) * N_;
#pragma unroll
    for (int i = 0; i < 8; i++) {
        size_t rb = ob + (size_t)(e0 + i) * N_;
#pragma unroll
        for (int k = 0; k < 4; k++) {
            int n = n0 + lane + 32 * k;
            if (n < N_) g_img[rb + n] = acc[i][k];
        }
    }
}

// ---------------------------------------------------------------------------
// Kernel 4: depthwise 3x3 conv, SAME padding, on [B,C,56,56] -> [B,C,56,56]
// ---------------------------------------------------------------------------
__global__ __launch_bounds__(256) void dwconv_kernel(
    const float* __restrict__ w, const float* __restrict__ bias)
{
    size_t gid = (size_t)blockIdx.x * 256 + threadIdx.x;
    if (gid >= (size_t)B_ * C_ * N_) return;
    int n  = (int)(gid % N_);
    int bc = (int)(gid / N_);
    int c  = bc % C_;
    int y = n / 56, x = n % 56;

    const float* wp = w + c * 9;
    const float* ip = g_img + (size_t)bc * N_;
    float acc = bias[c];
#pragma unroll
    for (int ky = 0; ky < 3; ky++) {
        int yy = y + ky - 1;
        if (yy < 0 || yy >= 56) continue;
#pragma unroll
        for (int kx = 0; kx < 3; kx++) {
            int xx = x + kx - 1;
            if (xx < 0 || xx >= 56) continue;
            acc += ip[yy * 56 + xx] * wp[ky * 3 + kx];
        }
    }
    g_cnv[gid] = acc;
}

// ---------------------------------------------------------------------------
// Kernel 5: proj GEMM  out[M,768] = A[M,768] @ proj_w[768,768] + proj_b
// A is g_cnv in [B, C, N] layout: A(m,k) = g_cnv[(b*768+k)*3136 + n], m=b*N+n.
// k-major in memory -> direct [k][m] smem stores, float4 along m.
// 128x128x16, double-buffered.
// ---------------------------------------------------------------------------
__global__ __launch_bounds__(256, 2) void proj_gemm_kernel(
    const float* __restrict__ W, const float* __restrict__ bias,
    float* __restrict__ out)
{
    constexpr int BK = 16;
    __shared__ float As[2][BK][128];   // [k][m]
    __shared__ float Bs[2][BK][128];   // [k][n]

    const int tid = threadIdx.x;
    const int m0 = blockIdx.y * 128;
    const int n0 = blockIdx.x * 128;

    const int tr = (tid >> 4) * 8;
    const int tc = (tid & 15) * 8;

    const int aRow = tid >> 4;          // k 0..15
    const int aCol = (tid & 15) * 8;    // m 0..120
    const int bRow = tid >> 4;          // k 0..15
    const int bCol = (tid & 15) * 8;    // n 0..120

    // Two float4 bases along m; each float4 stays inside one batch (batch
    // boundary multiples of 3136 are 0 mod 8; chunks are 8-aligned).
    const int m1 = m0 + aCol;
    const int ab1 = m1 / N_;
    const int an1 = m1 - ab1 * N_;
    const int m2 = m1 + 4;
    const int ab2 = m2 / N_;
    const int an2 = m2 - ab2 * N_;
    const float* Ap1 = g_cnv + (size_t)ab1 * C_ * N_ + an1;
    const float* Ap2 = g_cnv + (size_t)ab2 * C_ * N_ + an2;
    const float* Wp = W + (size_t)bRow * C_ + n0 + bCol;

    float4 fa0 = *(const float4*)(Ap1 + (size_t)aRow * N_);
    float4 fa1 = *(const float4*)(Ap2 + (size_t)aRow * N_);
    float4 fb0 = *(const float4*)(Wp);
    float4 fb1 = *(const float4*)(Wp + 4);

    float acc[8][8];
#pragma unroll
    for (int i = 0; i < 8; i++)
#pragma unroll
        for (int j = 0; j < 8; j++) acc[i][j] = 0.f;

    *(float4*)&As[0][aRow][aCol]     = fa0;
    *(float4*)&As[0][aRow][aCol + 4] = fa1;
    *(float4*)&Bs[0][bRow][bCol]     = fb0;
    *(float4*)&Bs[0][bRow][bCol + 4] = fb1;
    __syncthreads();

    int buf = 0;
    for (int kt = 0; kt < 768; kt += BK) {
        const int ktn = kt + BK;
        if (ktn < 768) {
            fa0 = *(const float4*)(Ap1 + (size_t)(ktn + aRow) * N_);
            fa1 = *(const float4*)(Ap2 + (size_t)(ktn + aRow) * N_);
            fb0 = *(const float4*)(Wp + (size_t)ktn * C_);
            fb1 = *(const float4*)(Wp + (size_t)ktn * C_ + 4);
        }

#pragma unroll
        for (int k = 0; k < BK; k++) {
            float ra[8], rb[8];
            *(float4*)&ra[0] = *(const float4*)&As[buf][k][tr];
            *(float4*)&ra[4] = *(const float4*)&As[buf][k][tr + 4];
            *(float4*)&rb[0] = *(const float4*)&Bs[buf][k][tc];
            *(float4*)&rb[4] = *(const float4*)&Bs[buf][k][tc + 4];
#pragma unroll
            for (int i = 0; i < 8; i++)
#pragma unroll
                for (int j = 0; j < 8; j++) acc[i][j] += ra[i] * rb[j];
        }

        if (ktn < 768) {
            const int nb = buf ^ 1;
            *(float4*)&As[nb][aRow][aCol]     = fa0;
            *(float4*)&As[nb][aRow][aCol + 4] = fa1;
            *(float4*)&Bs[nb][bRow][bCol]     = fb0;
            *(float4*)&Bs[nb][bRow][bCol + 4] = fb1;
            __syncthreads();
            buf = nb;
        }
    }

    float bb[8];
#pragma unroll
    for (int j = 0; j < 8; j++) bb[j] = bias[n0 + tc + j];

#pragma unroll
    for (int i = 0; i < 8; i++) {
        size_t ob = (size_t)(m0 + tr + i) * C_ + n0 + tc;
        float4 v0, v1;
        v0.x = acc[i][0] + bb[0]; v0.y = acc[i][1] + bb[1];
        v0.z = acc[i][2] + bb[2]; v0.w = acc[i][3] + bb[3];
        v1.x = acc[i][4] + bb[4]; v1.y = acc[i][5] + bb[5];
        v1.z = acc[i][6] + bb[6]; v1.w = acc[i][7] + bb[7];
        *(float4*)&out[ob]     = v0;
        *(float4*)&out[ob + 4] = v1;
    }
}

// ---------------------------------------------------------------------------
extern "C" void kernel_launch(void* const* d_in, const int* in_sizes, int n_in,
                              void* d_out, int out_size)
{
    const float* x      = (const float*)d_in[0];
    const float* qkv_w  = (const float*)d_in[1];
    const float* qkv_b  = (const float*)d_in[2];
    const float* dw_w   = (const float*)d_in[3];
    const float* dw_b   = (const float*)d_in[4];
    const float* proj_w = (const float*)d_in[5];
    const float* proj_b = (const float*)d_in[6];
    float* out = (float*)d_out;

    // 1) QKV GEMM: [50176,768] x [768,2304]
    qkv_gemm_kernel<<<dim3(QC_ / 128, M_ / 128), 256>>>(x, qkv_w, qkv_b);

    // 2) context per (b,h)
    ctx_kernel<<<B_ * H_, 256>>>();

    // 3) q @ ctx -> [B,C,N]
    attn_out_kernel<<<dim3((N_ + 127) / 128, H_, B_), 256>>>();

    // 4) depthwise conv
    dwconv_kernel<<<(unsigned)(((size_t)B_ * C_ * N_ + 255) / 256), 256>>>(dw_w, dw_b);

    // 5) proj GEMM: [50176,768] x [768,768]
    proj_gemm_kernel<<<dim3(C_ / 128, M_ / 128), 256>>>(proj_w, proj_b, out);
}

// round 16
// speedup vs baseline: 1.5812x; 1.5812x over previous
#include <cuda_runtime.h>
#include <cuda_bf16.h>

// Problem constants
static constexpr int B_  = 16;
static constexpr int N_  = 3136;   // 56*56
static constexpr int C_  = 768;
static constexpr int H_  = 12;
static constexpr int D_  = 64;
static constexpr int M_  = B_ * N_;          // 50176
static constexpr int QC_ = 3 * C_;           // 2304

// Scratch (static device globals)
__device__ float g_qkv[(size_t)M_ * QC_];          // [M, 2304]
__device__ float g_ctx[(size_t)B_ * H_ * D_ * D_]; // [B*H,64,64]
__device__ float g_img[(size_t)B_ * C_ * N_];      // [B,C,N] attn out
__device__ float g_cnv[(size_t)B_ * C_ * N_];      // [B,C,N] conv out
// Pre-converted bf16 hi/lo operands (16B-aligned: loaders use uint4)
__device__ __align__(16) __nv_bfloat16 g_xh[(size_t)M_ * C_];    // x hi  [M,768]
__device__ __align__(16) __nv_bfloat16 g_xl[(size_t)M_ * C_];    // x lo
__device__ __align__(16) __nv_bfloat16 g_wqh[(size_t)QC_ * C_];  // qkv_w^T hi [2304,768]
__device__ __align__(16) __nv_bfloat16 g_wql[(size_t)QC_ * C_];
__device__ __align__(16) __nv_bfloat16 g_wph[(size_t)C_ * C_];   // proj_w^T hi [768,768]
__device__ __align__(16) __nv_bfloat16 g_wpl[(size_t)C_ * C_];
__device__ __align__(16) __nv_bfloat16 g_cth[(size_t)M_ * C_];   // conv out^T hi [B,N,C]
__device__ __align__(16) __nv_bfloat16 g_ctl[(size_t)M_ * C_];

// ===========================================================================
// mma.sync helpers (standard sm_80+ features)
// ===========================================================================
__device__ __forceinline__ unsigned smem_u32(const void* p) {
    unsigned a;
    asm("{ .reg .u64 t; cvta.to.shared.u64 t, %1; cvt.u32.u64 %0, t; }"
        : "=r"(a) : "l"(p));
    return a;
}

__device__ __forceinline__ void ldm_x4(unsigned addr, unsigned r[4]) {
    asm volatile("ldmatrix.sync.aligned.m8n8.x4.shared.b16 {%0,%1,%2,%3}, [%4];"
                 : "=r"(r[0]), "=r"(r[1]), "=r"(r[2]), "=r"(r[3]) : "r"(addr));
}
__device__ __forceinline__ void mma_bf16(float c[4], const unsigned a[4],
                                         unsigned b0, unsigned b1) {
    asm volatile(
        "mma.sync.aligned.m16n8k16.row.col.f32.bf16.bf16.f32 "
        "{%0,%1,%2,%3}, {%4,%5,%6,%7}, {%8,%9}, {%0,%1,%2,%3};"
        : "+f"(c[0]), "+f"(c[1]), "+f"(c[2]), "+f"(c[3])
        : "r"(a[0]), "r"(a[1]), "r"(a[2]), "r"(a[3]), "r"(b0), "r"(b1));
}

// hi/lo bf16 split of two floats, packed along k
__device__ __forceinline__ void split2(float a, float b, unsigned& h, unsigned& l) {
    __nv_bfloat16 ah = __float2bfloat16(a);
    __nv_bfloat16 bh = __float2bfloat16(b);
    __nv_bfloat16 al = __float2bfloat16(a - __bfloat162float(ah));
    __nv_bfloat16 bl = __float2bfloat16(b - __bfloat162float(bh));
    __nv_bfloat162 hv = __halves2bfloat162(ah, bh);
    __nv_bfloat162 lv = __halves2bfloat162(al, bl);
    h = *reinterpret_cast<unsigned*>(&hv);
    l = *reinterpret_cast<unsigned*>(&lv);
}

// SMEM tile geometry: [128 rows][32 k] bf16, row pitch 40 bf16 (80 B)
// Pitch 80B: the 8 m8n8 row addresses land on word-banks r*20 mod 32 =
// {0,20,8,28,16,4,24,12} (4 banks each) -> all 32 banks exactly once;
// ldmatrix is conflict-free without a swizzle.
static constexpr int TP   = 40;                 // tile pitch (bf16)
static constexpr int TPB  = TP * 2;             // 80 bytes
static constexpr int TSZ  = 128 * TPB;          // 10240 B per tile
static constexpr int O_AH = 0;
static constexpr int O_AL = TSZ;
static constexpr int O_BH = 2 * TSZ;
static constexpr int O_BL = 3 * TSZ;
static constexpr int BUFB = 4 * TSZ;            // 40960 B per buffer
static constexpr int SMEM_GEMM = 2 * BUFB;      // 81920 B

// ===========================================================================
// bf16-split HMMA GEMM: out tile 128x128 of A[M,768] @ Bt[N',768]^T
// A, Bt row-major bf16 hi/lo (pitch 768). 256 threads, 8 warps (4m x 2n),
// warp tile 32x64, k-chunk 32, double-buffered smem + register prefetch.
// B stored n-major (k contiguous) == col-major KxN: NON-trans ldmatrix gives
// the row.col B fragment directly (consecutive-k pair per register, n = t/4).
// ===========================================================================
__device__ __forceinline__ void hmma_gemm_tile(
    const __nv_bfloat16* ah, const __nv_bfloat16* al,
    const __nv_bfloat16* bh, const __nv_bfloat16* bl,
    int m0, int n0, const float* __restrict__ bias,
    float* __restrict__ outp, int out_pitch, char* smem)
{
    const int tid  = threadIdx.x;
    const int lane = tid & 31;
    const int wid  = tid >> 5;
    const int wm   = wid & 3;         // warp m index (0..3) -> 32 rows
    const int wn   = wid >> 2;        // warp n index (0..1) -> 64 cols
    const unsigned sb = smem_u32(smem);

    // loader assignment: 512 chunks (row=c>>2, q=c&3); thread does c=tid, tid+256
    const int r0 = tid >> 2, q = tid & 3;
    const int r1 = r0 + 64;
    const size_t gq = (size_t)q * 16;  // byte offset within 64B k-row chunk

    const char* pAh0 = (const char*)ah + (size_t)(m0 + r0) * 1536;
    const char* pAh1 = (const char*)ah + (size_t)(m0 + r1) * 1536;
    const char* pAl0 = (const char*)al + (size_t)(m0 + r0) * 1536;
    const char* pAl1 = (const char*)al + (size_t)(m0 + r1) * 1536;
    const char* pBh0 = (const char*)bh + (size_t)(n0 + r0) * 1536;
    const char* pBh1 = (const char*)bh + (size_t)(n0 + r1) * 1536;
    const char* pBl0 = (const char*)bl + (size_t)(n0 + r0) * 1536;
    const char* pBl1 = (const char*)bl + (size_t)(n0 + r1) * 1536;

    const unsigned s0 = (unsigned)(r0 * TPB + q * 16);
    const unsigned s1 = (unsigned)(r1 * TPB + q * 16);

    float c[2][8][4];
#pragma unroll
    for (int i = 0; i < 2; i++)
#pragma unroll
        for (int j = 0; j < 8; j++)
#pragma unroll
            for (int k = 0; k < 4; k++) c[i][j][k] = 0.f;

    // prefetch tile 0
    uint4 va0 = *(const uint4*)(pAh0 + gq), va1 = *(const uint4*)(pAh1 + gq);
    uint4 vb0 = *(const uint4*)(pAl0 + gq), vb1 = *(const uint4*)(pAl1 + gq);
    uint4 vc0 = *(const uint4*)(pBh0 + gq), vc1 = *(const uint4*)(pBh1 + gq);
    uint4 vd0 = *(const uint4*)(pBl0 + gq), vd1 = *(const uint4*)(pBl1 + gq);

    *(uint4*)(smem + O_AH + s0) = va0;  *(uint4*)(smem + O_AH + s1) = va1;
    *(uint4*)(smem + O_AL + s0) = vb0;  *(uint4*)(smem + O_AL + s1) = vb1;
    *(uint4*)(smem + O_BH + s0) = vc0;  *(uint4*)(smem + O_BH + s1) = vc1;
    *(uint4*)(smem + O_BL + s0) = vd0;  *(uint4*)(smem + O_BL + s1) = vd1;
    __syncthreads();

    // ldmatrix lane address components (lanes 0-15: rows, k-bytes 0;
    // lanes 16-31: same rows, k-bytes +16)
    const unsigned lrow = (unsigned)(lane & 15);
    const unsigned lhalf = (unsigned)((lane >> 4) << 4);

    int buf = 0;
    for (int kt = 0; kt < 768; kt += 32) {
        const int ktn = kt + 32;
        if (ktn < 768) {
            const size_t go = (size_t)ktn * 2 + gq;
            va0 = *(const uint4*)(pAh0 + go);  va1 = *(const uint4*)(pAh1 + go);
            vb0 = *(const uint4*)(pAl0 + go);  vb1 = *(const uint4*)(pAl1 + go);
            vc0 = *(const uint4*)(pBh0 + go);  vc1 = *(const uint4*)(pBh1 + go);
            vd0 = *(const uint4*)(pBl0 + go);  vd1 = *(const uint4*)(pBl1 + go);
        }

        const unsigned base = sb + buf * BUFB;
#pragma unroll
        for (int ks = 0; ks < 32; ks += 16) {
            // A fragments: 2 m-tiles, hi & lo
            unsigned a_h[2][4], a_l[2][4];
#pragma unroll
            for (int mt = 0; mt < 2; mt++) {
                unsigned row = (unsigned)(wm * 32 + mt * 16) + lrow;
                unsigned off = row * TPB + (unsigned)(ks * 2) + lhalf;
                ldm_x4(base + O_AH + off, a_h[mt]);
                ldm_x4(base + O_AL + off, a_l[mt]);
            }
            // B: 4 groups of n16 (each covers 2 n8-tiles), NON-trans:
            // r0 = n-rows 0-7 @ k0-7, r1 = n-rows 8-15 @ k0-7,
            // r2/r3 = same rows @ k8-15.
#pragma unroll
            for (int g = 0; g < 4; g++) {
                unsigned brow = (unsigned)(wn * 64 + g * 16) + lrow;
                unsigned boff = brow * TPB + (unsigned)(ks * 2) + lhalf;
                unsigned b_h[4], b_l[4];
                ldm_x4(base + O_BH + boff, b_h);
                ldm_x4(base + O_BL + boff, b_l);
#pragma unroll
                for (int mt = 0; mt < 2; mt++) {
                    // n8 tile 2g   : {b[0], b[2]}
                    mma_bf16(c[mt][2 * g],     a_h[mt], b_h[0], b_h[2]);
                    mma_bf16(c[mt][2 * g],     a_h[mt], b_l[0], b_l[2]);
                    mma_bf16(c[mt][2 * g],     a_l[mt], b_h[0], b_h[2]);
                    // n8 tile 2g+1 : {b[1], b[3]}
                    mma_bf16(c[mt][2 * g + 1], a_h[mt], b_h[1], b_h[3]);
                    mma_bf16(c[mt][2 * g + 1], a_h[mt], b_l[1], b_l[3]);
                    mma_bf16(c[mt][2 * g + 1], a_l[mt], b_h[1], b_h[3]);
                }
            }
        }

        if (ktn < 768) {
            __syncthreads();
            const int nb = buf ^ 1;
            char* d = smem + nb * BUFB;
            *(uint4*)(d + O_AH + s0) = va0;  *(uint4*)(d + O_AH + s1) = va1;
            *(uint4*)(d + O_AL + s0) = vb0;  *(uint4*)(d + O_AL + s1) = vb1;
            *(uint4*)(d + O_BH + s0) = vc0;  *(uint4*)(d + O_BH + s1) = vc1;
            *(uint4*)(d + O_BL + s0) = vd0;  *(uint4*)(d + O_BL + s1) = vd1;
            __syncthreads();
            buf = nb;
        }
    }

    // Epilogue: fragment c layout (m16n8): rows lane>>2 (+8), cols (lane&3)*2
    const int crow = lane >> 2;
    const int ccol = (lane & 3) * 2;
#pragma unroll
    for (int mt = 0; mt < 2; mt++) {
        const int gm = m0 + wm * 32 + mt * 16;
#pragma unroll
        for (int nt = 0; nt < 8; nt++) {
            const int gn = n0 + wn * 64 + nt * 8 + ccol;
            float2 bb = *(const float2*)(bias + gn);
            float2 v0, v1;
            v0.x = c[mt][nt][0] + bb.x;  v0.y = c[mt][nt][1] + bb.y;
            v1.x = c[mt][nt][2] + bb.x;  v1.y = c[mt][nt][3] + bb.y;
            *(float2*)&outp[(size_t)(gm + crow) * out_pitch + gn]     = v0;
            *(float2*)&outp[(size_t)(gm + crow + 8) * out_pitch + gn] = v1;
        }
    }
}

__global__ void __launch_bounds__(256) qkv_mma_kernel(const float* __restrict__ bias)
{
    extern __shared__ char smem[];
    hmma_gemm_tile(g_xh, g_xl, g_wqh, g_wql,
                   blockIdx.y * 128, blockIdx.x * 128, bias, g_qkv, QC_, smem);
}

__global__ void __launch_bounds__(256) proj_mma_kernel(const float* __restrict__ bias,
                                                       float* __restrict__ out)
{
    extern __shared__ char smem[];
    hmma_gemm_tile(g_cth, g_ctl, g_wph, g_wpl,
                   blockIdx.y * 128, blockIdx.x * 128, bias, out, C_, smem);
}

// ===========================================================================
// Pre-pass 1: x [M,768] f32 -> g_xh/g_xl bf16 row-major (elementwise)
// ===========================================================================
__global__ __launch_bounds__(256) void convert_x_kernel(const float* __restrict__ x)
{
    size_t i4 = (size_t)blockIdx.x * 256 + threadIdx.x;   // float4 index
    if (i4 >= (size_t)M_ * C_ / 4) return;
    float4 v = ((const float4*)x)[i4];
    uint2 h, l;
    split2(v.x, v.y, h.x, l.x);
    split2(v.z, v.w, h.y, l.y);
    ((uint2*)g_xh)[i4] = h;
    ((uint2*)g_xl)[i4] = l;
}

// ===========================================================================
// Pre-pass 2: weight transpose-convert  W[768,ncols] f32 -> Wt[ncols,768] bf16
// ===========================================================================
__global__ __launch_bounds__(1024) void wtrans_kernel(
    const float* __restrict__ src, int ncols,
    __nv_bfloat16* __restrict__ dh, __nv_bfloat16* __restrict__ dl)
{
    __shared__ float s[32][33];
    const int k0 = blockIdx.y * 32, n0 = blockIdx.x * 32;
    const int tx = threadIdx.x, ty = threadIdx.y;
    s[ty][tx] = src[(size_t)(k0 + ty) * ncols + n0 + tx];
    __syncthreads();
    if (tx < 16) {
        unsigned h, l;
        split2(s[tx * 2][ty], s[tx * 2 + 1][ty], h, l);
        size_t o = ((size_t)(n0 + ty) * 768 + k0) / 2 + tx;  // u32 index
        ((unsigned*)dh)[o] = h;
        ((unsigned*)dl)[o] = l;
    }
}

// ===========================================================================
// Pre-pass 3: conv-out transpose-convert [B,C,N] f32 -> [B,N,C] bf16 hi/lo
// ===========================================================================
__global__ __launch_bounds__(1024) void cnvt_kernel()
{
    __shared__ float s[32][33];
    const int b = blockIdx.z;
    const int c0 = blockIdx.y * 32, n0 = blockIdx.x * 32;
    const int tx = threadIdx.x, ty = threadIdx.y;
    s[ty][tx] = g_cnv[((size_t)b * C_ + c0 + ty) * N_ + n0 + tx];
    __syncthreads();
    if (tx < 16) {
        unsigned h, l;
        split2(s[tx * 2][ty], s[tx * 2 + 1][ty], h, l);
        size_t o = (((size_t)b * N_ + n0 + ty) * C_ + c0) / 2 + tx;
        ((unsigned*)g_cth)[o] = h;
        ((unsigned*)g_ctl)[o] = l;
    }
}

// ---------------------------------------------------------------------------
// context[b,h] = relu(k)^T @ v   ([64,64] per (b,h))
// ---------------------------------------------------------------------------
__global__ __launch_bounds__(256) void ctx_kernel()
{
    const int bh = blockIdx.x;
    const int b = bh / H_;
    const int h = bh - b * H_;
    const int tid = threadIdx.x;

    __shared__ float ks[32][64];
    __shared__ float vs[32][64];

    float acc[4][4];
#pragma unroll
    for (int i = 0; i < 4; i++)
#pragma unroll
        for (int j = 0; j < 4; j++) acc[i][j] = 0.f;

    const int rg = (tid >> 4) * 4;
    const int cg = (tid & 15) * 4;

    const size_t kbase = (size_t)b * N_ * QC_ + 768 + h * 64;

    for (int nt = 0; nt < N_; nt += 32) {
#pragma unroll
        for (int i = 0; i < 2; i++) {
            int idx = tid + i * 256;
            int row = idx >> 4;
            int col = (idx & 15) * 4;
            size_t p = kbase + (size_t)(nt + row) * QC_ + col;
            float4 kv = *(const float4*)(g_qkv + p);
            float4 vv = *(const float4*)(g_qkv + p + 768);
            kv.x = fmaxf(kv.x, 0.f); kv.y = fmaxf(kv.y, 0.f);
            kv.z = fmaxf(kv.z, 0.f); kv.w = fmaxf(kv.w, 0.f);
            *(float4*)&ks[row][col] = kv;
            *(float4*)&vs[row][col] = vv;
        }
        __syncthreads();

#pragma unroll 8
        for (int nn = 0; nn < 32; nn++) {
            float kr[4], vr[4];
            *(float4*)kr = *(const float4*)&ks[nn][rg];
            *(float4*)vr = *(const float4*)&vs[nn][cg];
#pragma unroll
            for (int i = 0; i < 4; i++)
#pragma unroll
                for (int j = 0; j < 4; j++) acc[i][j] += kr[i] * vr[j];
        }
        __syncthreads();
    }

    size_t ob = (size_t)bh * (D_ * D_);
#pragma unroll
    for (int i = 0; i < 4; i++) {
        float4 v;
        v.x = acc[i][0]; v.y = acc[i][1]; v.z = acc[i][2]; v.w = acc[i][3];
        *(float4*)&g_ctx[ob + (size_t)(rg + i) * 64 + cg] = v;
    }
}

// ---------------------------------------------------------------------------
// attn out: [b, h*64+e, n] = sum_d relu(q)*scale * ctx -> [B,C,N]
// ---------------------------------------------------------------------------
__global__ __launch_bounds__(256) void attn_out_kernel()
{
    const int n0 = blockIdx.x * 128;
    const int h  = blockIdx.y;
    const int b  = blockIdx.z;
    const int tid = threadIdx.x;

    __shared__ float cs[64][64];
    __shared__ float qs[64][129];

    const size_t cb = (size_t)(b * H_ + h) * (D_ * D_);
#pragma unroll
    for (int i = 0; i < 4; i++) {
        int idx = tid + i * 256;
        ((float4*)&cs[0][0])[idx] = ((const float4*)(g_ctx + cb))[idx];
    }

    const float scale = 0.125f;
#pragma unroll
    for (int i = 0; i < 32; i++) {
        int idx = tid + i * 256;
        int d  = idx & 63;
        int nn = idx >> 6;
        int n  = n0 + nn;
        float v = 0.f;
        if (n < N_)
            v = g_qkv[(size_t)(b * N_ + n) * QC_ + h * 64 + d];
        qs[d][nn] = fmaxf(v, 0.f) * scale;
    }
    __syncthreads();

    const int lane = tid & 31;
    const int e0 = (tid >> 5) * 8;
    float acc[8][4];
#pragma unroll
    for (int i = 0; i < 8; i++)
#pragma unroll
        for (int k = 0; k < 4; k++) acc[i][k] = 0.f;

#pragma unroll 4
    for (int dd = 0; dd < 64; dd++) {
        float qv[4];
#pragma unroll
        for (int k = 0; k < 4; k++) qv[k] = qs[dd][lane + 32 * k];
#pragma unroll
        for (int i = 0; i < 8; i++) {
            float ce = cs[dd][e0 + i];
#pragma unroll
            for (int k = 0; k < 4; k++) acc[i][k] += ce * qv[k];
        }
    }

    const size_t ob = ((size_t)b * C_ + h * 64) * N_;
#pragma unroll
    for (int i = 0; i < 8; i++) {
        size_t rb = ob + (size_t)(e0 + i) * N_;
#pragma unroll
        for (int k = 0; k < 4; k++) {
            int n = n0 + lane + 32 * k;
            if (n < N_) g_img[rb + n] = acc[i][k];
        }
    }
}

// ---------------------------------------------------------------------------
// depthwise 3x3 conv, SAME padding, [B,C,56,56] -> [B,C,56,56]
// ---------------------------------------------------------------------------
__global__ __launch_bounds__(256) void dwconv_kernel(
    const float* __restrict__ w, const float* __restrict__ bias)
{
    size_t gid = (size_t)blockIdx.x * 256 + threadIdx.x;
    if (gid >= (size_t)B_ * C_ * N_) return;
    int n  = (int)(gid % N_);
    int bc = (int)(gid / N_);
    int c  = bc % C_;
    int y = n / 56, x = n % 56;

    const float* wp = w + c * 9;
    const float* ip = g_img + (size_t)bc * N_;
    float acc = bias[c];
#pragma unroll
    for (int ky = 0; ky < 3; ky++) {
        int yy = y + ky - 1;
        if (yy < 0 || yy >= 56) continue;
#pragma unroll
        for (int kx = 0; kx < 3; kx++) {
            int xx = x + kx - 1;
            if (xx < 0 || xx >= 56) continue;
            acc += ip[yy * 56 + xx] * wp[ky * 3 + kx];
        }
    }
    g_cnv[gid] = acc;
}

// ---------------------------------------------------------------------------
extern "C" void kernel_launch(void* const* d_in, const int* in_sizes, int n_in,
                              void* d_out, int out_size)
{
    const float* x      = (const float*)d_in[0];
    const float* qkv_w  = (const float*)d_in[1];
    const float* qkv_b  = (const float*)d_in[2];
    const float* dw_w   = (const float*)d_in[3];
    const float* dw_b   = (const float*)d_in[4];
    const float* proj_w = (const float*)d_in[5];
    const float* proj_b = (const float*)d_in[6];
    float* out = (float*)d_out;

    cudaFuncSetAttribute(qkv_mma_kernel,
                         cudaFuncAttributeMaxDynamicSharedMemorySize, SMEM_GEMM);
    cudaFuncSetAttribute(proj_mma_kernel,
                         cudaFuncAttributeMaxDynamicSharedMemorySize, SMEM_GEMM);

    __nv_bfloat16 *wqh, *wql, *wph, *wpl;
    cudaGetSymbolAddress((void**)&wqh, g_wqh);
    cudaGetSymbolAddress((void**)&wql, g_wql);
    cudaGetSymbolAddress((void**)&wph, g_wph);
    cudaGetSymbolAddress((void**)&wpl, g_wpl);

    // Pre-passes: convert x; transpose+convert weights
    convert_x_kernel<<<(unsigned)(((size_t)M_ * C_ / 4 + 255) / 256), 256>>>(x);
    wtrans_kernel<<<dim3(QC_ / 32, C_ / 32), dim3(32, 32)>>>(qkv_w, QC_, wqh, wql);
    wtrans_kernel<<<dim3(C_ / 32, C_ / 32), dim3(32, 32)>>>(proj_w, C_, wph, wpl);

    // 1) QKV GEMM (bf16-split HMMA)
    qkv_mma_kernel<<<dim3(QC_ / 128, M_ / 128), 256, SMEM_GEMM>>>(qkv_b);

    // 2) context per (b,h)
    ctx_kernel<<<B_ * H_, 256>>>();

    // 3) q @ ctx -> [B,C,N]
    attn_out_kernel<<<dim3((N_ + 127) / 128, H_, B_), 256>>>();

    // 4) depthwise conv
    dwconv_kernel<<<(unsigned)(((size_t)B_ * C_ * N_ + 255) / 256), 256>>>(dw_w, dw_b);

    // 4b) transpose+convert conv out for proj A operand
    cnvt_kernel<<<dim3(N_ / 32, C_ / 32, B_), dim3(32, 32)>>>();

    // 5) proj GEMM (bf16-split HMMA)
    proj_mma_kernel<<<dim3(C_ / 128, M_ / 128), 256, SMEM_GEMM>>>(proj_b, out);
}